// round 1
// baseline (speedup 1.0000x reference)
#include <cuda_runtime.h>

// Problem constants
#define NB 16
#define CI 32
#define CO 32
#define HH 224
#define WW 224
#define TILE_H 8
#define TILE_W 32
#define GX 7     // 224 / TILE_W
#define GY 28    // 224 / TILE_H
#define NBLK (GX*GY*NB)   // 3136 conv blocks

// Scratch (no allocations allowed -> __device__ globals)
__device__ double g_part[NBLK * 64];     // per-block per-channel [sum(0..31), sumsq(32..63)]
__device__ float  g_scale[CO];
__device__ float  g_bias[CO];

// ---------------------------------------------------------------------------
// Conv: binarized-weight 3x3, pad 1. One block = (n, 8h x 32w) tile, all 32
// output channels. Warp = 32 output channels at same h -> xs LDS broadcast.
// Also emits per-block per-channel sum/sumsq (double, fixed-order -> deterministic).
// ---------------------------------------------------------------------------
__global__ __launch_bounds__(256, 2)
void conv_kernel(const float* __restrict__ x, const float* __restrict__ wgt,
                 float* __restrict__ out)
{
    extern __shared__ float smem[];
    float* ws = smem;                 // 32 * 289  (pitch 289: kills 32-way bank conflict)
    float* xs = smem + 32 * 289;      // 32 c * 10 rows * 36 cols (pitch 36 -> 16B aligned rows)
    __shared__ double sred[512];

    const int tid = threadIdx.x;
    const int o   = tid & 31;         // output channel
    const int hg  = tid >> 5;         // row within tile (0..7)
    const int w0  = blockIdx.x * TILE_W;
    const int h0  = blockIdx.y * TILE_H;
    const int n   = blockIdx.z;

    // Binarize weights into shared (OIHW order, per-o pitch 289)
    for (int i = tid; i < CO * CI * 9; i += 256) {
        int oo = i / 288;
        int j  = i - oo * 288;
        ws[oo * 289 + j] = (wgt[i] >= 0.0f) ? 1.0f : -1.0f;
    }
    // Input tile with halo, zero-padded. 32 x 10 x 36 (cols 34..35 only to init vec-load tail)
    for (int i = tid; i < CI * 10 * 36; i += 256) {
        int c   = i / 360;
        int rem = i - c * 360;
        int rr  = rem / 36;
        int cc  = rem - rr * 36;
        int gh = h0 + rr - 1;
        int gw = w0 + cc - 1;
        float v = 0.0f;
        if (gh >= 0 && gh < HH && gw >= 0 && gw < WW)
            v = x[((n * CI + c) * HH + gh) * WW + gw];
        xs[c * 360 + rr * 36 + cc] = v;
    }
    __syncthreads();

    float acc[32];
#pragma unroll
    for (int i = 0; i < 32; i++) acc[i] = 0.0f;

#pragma unroll 1
    for (int c = 0; c < CI; c++) {
        float wv[9];
#pragma unroll
        for (int k = 0; k < 9; k++) wv[k] = ws[o * 289 + c * 9 + k];

#pragma unroll
        for (int dy = 0; dy < 3; dy++) {
            const float4* rp = (const float4*)&xs[c * 360 + (hg + dy) * 36];
            float r[36];
#pragma unroll
            for (int q = 0; q < 9; q++) {
                float4 t = rp[q];
                r[q*4+0] = t.x; r[q*4+1] = t.y; r[q*4+2] = t.z; r[q*4+3] = t.w;
            }
#pragma unroll
            for (int dx = 0; dx < 3; dx++) {
                float wcoef = wv[dy * 3 + dx];
#pragma unroll
                for (int wx = 0; wx < 32; wx++)
                    acc[wx] = fmaf(r[wx + dx], wcoef, acc[wx]);
            }
        }
    }

    // Write conv output (contiguous 128B per thread, vectorized)
    const int base = ((n * CO + o) * HH + (h0 + hg)) * WW + w0;
    float4* op = (float4*)&out[base];
#pragma unroll
    for (int q = 0; q < 8; q++) {
        float4 t;
        t.x = acc[q*4+0]; t.y = acc[q*4+1]; t.z = acc[q*4+2]; t.w = acc[q*4+3];
        op[q] = t;
    }

    // Per-thread stats in double, then fixed-order intra-block reduction
    double s = 0.0, ssq = 0.0;
#pragma unroll
    for (int i = 0; i < 32; i++) {
        double v = (double)acc[i];
        s   += v;
        ssq += v * v;
    }
    sred[o * 8 + hg]       = s;
    sred[256 + o * 8 + hg] = ssq;
    __syncthreads();

    const int bflat = blockIdx.x + GX * (blockIdx.y + GY * blockIdx.z);
    if (tid < 64) {
        int cch   = tid & 31;
        int which = tid >> 5;           // 0 = sum, 1 = sumsq
        double a = 0.0;
#pragma unroll
        for (int j = 0; j < 8; j++)     // fixed order -> deterministic
            a += sred[which * 256 + cch * 8 + j];
        g_part[bflat * 64 + which * 32 + cch] = a;
    }
}

// ---------------------------------------------------------------------------
// Reduce per-block partials -> per-channel BN scale/bias (deterministic tree)
// ---------------------------------------------------------------------------
__global__ void reduce_kernel(const float* __restrict__ gamma,
                              const float* __restrict__ beta)
{
    const int c = blockIdx.x;     // 32 blocks
    const int t = threadIdx.x;    // 256 threads
    __shared__ double sh[512];

    double s = 0.0, ssq = 0.0;
    for (int b = t; b < NBLK; b += 256) {
        s   += g_part[b * 64 + c];
        ssq += g_part[b * 64 + 32 + c];
    }
    sh[t]       = s;
    sh[256 + t] = ssq;
    __syncthreads();
    for (int step = 128; step > 0; step >>= 1) {
        if (t < step) {
            sh[t]       += sh[t + step];
            sh[256 + t] += sh[256 + t + step];
        }
        __syncthreads();
    }
    if (t == 0) {
        const double Nc   = (double)NB * HH * WW;
        double mean = sh[0] / Nc;
        double var  = sh[256] / Nc - mean * mean;
        double inv  = 1.0 / sqrt(var + 1e-5);
        double sc   = (double)gamma[c] * inv;
        g_scale[c] = (float)sc;
        g_bias[c]  = (float)((double)beta[c] - mean * sc);
    }
}

// ---------------------------------------------------------------------------
// Finalize: BN affine + hardtanh + 2-bit quantize (round-half-even), in place.
// 6,422,528 float4s = exactly 25088 blocks x 256 threads.
// ---------------------------------------------------------------------------
__device__ __forceinline__ float qclamp(float v, float sc, float bi)
{
    float y = fmaf(v, sc, bi);
    y = fminf(fmaxf(y, -1.0f), 1.0f);
    return rintf(y * 2.0f) * 0.5f;
}

__global__ void finalize_kernel(float4* __restrict__ out)
{
    const unsigned i = blockIdx.x * 256u + threadIdx.x;   // < 6422528
    const int c = (int)((i / 12544u) & 31u);              // 12544 float4s per (n,c) plane
    const float sc = g_scale[c];
    const float bi = g_bias[c];
    float4 v = out[i];
    v.x = qclamp(v.x, sc, bi);
    v.y = qclamp(v.y, sc, bi);
    v.z = qclamp(v.z, sc, bi);
    v.w = qclamp(v.w, sc, bi);
    out[i] = v;
}

// ---------------------------------------------------------------------------
extern "C" void kernel_launch(void* const* d_in, const int* in_sizes, int n_in,
                              void* d_out, int out_size)
{
    const float* x     = (const float*)d_in[0];   // (16,32,224,224)
    const float* wgt   = (const float*)d_in[1];   // (32,32,3,3) OIHW
    const float* gamma = (const float*)d_in[2];   // (32,)
    const float* beta  = (const float*)d_in[3];   // (32,)
    float* out = (float*)d_out;                   // (16,32,224,224)

    const size_t shmem = (size_t)(32 * 289 + 32 * 10 * 36) * sizeof(float);  // 83072 B
    cudaFuncSetAttribute(conv_kernel, cudaFuncAttributeMaxDynamicSharedMemorySize, (int)shmem);

    conv_kernel<<<dim3(GX, GY, NB), 256, shmem>>>(x, wgt, out);
    reduce_kernel<<<32, 256>>>(gamma, beta);
    finalize_kernel<<<25088, 256>>>((float4*)d_out);
}